// round 8
// baseline (speedup 1.0000x reference)
#include <cuda_runtime.h>
#include <stdint.h>
#include <math.h>

#define TT 2048
#define BB 16
#define NN 2048
#define HH 1024
#define SPL 32
#define CHUNK 64    // timesteps per CTA; 16 macro-iters of 4
#define THR 256     // k_main threads (8 warps)
#define STAGES 3

// scratch (device globals: no allocation allowed in kernel_launch)
__device__ float g_decfea[BB*NN];
__device__ float g_scores[TT*BB];
__device__ float g_m[BB*SPL];
__device__ float g_z[BB*SPL];
__device__ float g_acc[BB*SPL*NN];     // 4 MB
__device__ unsigned char g_mask8[TT*BB];

// single-MUFU tanh (sm_75+), abs err ~2e-4 — fine vs 1e-3 threshold
__device__ __forceinline__ float tanhfast(float x){
    float y;
    asm("tanh.approx.f32 %0, %1;" : "=f"(y) : "f"(x));
    return y;
}

__device__ __forceinline__ void cpasync16(unsigned int saddr, const float* g){
    asm volatile("cp.async.cg.shared.global [%0], [%1], 16;" :: "r"(saddr), "l"(g));
}
#define CP_COMMIT() asm volatile("cp.async.commit_group;" ::: "memory")
#define CP_WAIT(n)  asm volatile("cp.async.wait_group %0;" :: "n"(n) : "memory")

// ---------------------------------------------------------------------------
// Kernel 1: dec_fea[b,n] = dot(dec[b,:], Wd[n,:]) + bd[n].
// 256 CTAs x 256 thr; warp owns one n-row; all 16 dec batches staged once in
// 64 KB dynamic smem. Full-butterfly reduce; lane b stores batch b.
// Also converts the padding mask to uint8 (dtype auto-detected).
// ---------------------------------------------------------------------------
__global__ __launch_bounds__(256) void k_decfea(
    const float* __restrict__ dec,
    const float* __restrict__ Wd,
    const float* __restrict__ bd,
    const unsigned char* __restrict__ mraw){
    extern __shared__ float sdec[];    // 64 KB: all 16 batches of dec
    // ---- mask conversion (65536 lanes cover 32768 elems) ----
    {
        const unsigned int* w = (const unsigned int*)mraw;
        int is_word = 1;   // int32 (0/1) or float32 (0.0/1.0) storage
        #pragma unroll
        for (int i = 0; i < 32; ++i){
            unsigned int x = w[i];
            if (x != 0u && x != 1u && x != 0x3F800000u) is_word = 0;
        }
        int idx = blockIdx.x*256 + threadIdx.x;
        if (idx < TT*BB){
            unsigned char mv = is_word ? (unsigned char)(w[idx] != 0u)
                                       : (unsigned char)(mraw[idx] != 0);
            g_mask8[idx] = mv;
        }
    }

    int tid  = threadIdx.x;
    int wid  = tid >> 5, lane = tid & 31;

    // stage all of dec (16*1024 floats)
    {
        const float4* dg = (const float4*)dec;
        float4* sg = (float4*)sdec;
        #pragma unroll
        for (int i = 0; i < 16; ++i) sg[tid + i*256] = dg[tid + i*256];
    }
    __syncthreads();

    int n = blockIdx.x*8 + wid;        // this warp's row
    const float4* wp = (const float4*)(Wd + (size_t)n*HH);
    const float4* sd = (const float4*)sdec;

    float acc[BB];
    #pragma unroll
    for (int b = 0; b < BB; ++b) acc[b] = 0.f;

    #pragma unroll
    for (int ch = 0; ch < 8; ++ch){
        float4 wv = wp[ch*32 + lane];
        #pragma unroll
        for (int b = 0; b < BB; ++b){
            float4 d = sd[b*256 + ch*32 + lane];
            acc[b] += wv.x*d.x + wv.y*d.y + wv.z*d.z + wv.w*d.w;
        }
    }
    // full butterfly: every lane ends with all sums
    #pragma unroll
    for (int b = 0; b < BB; ++b){
        #pragma unroll
        for (int off = 16; off; off >>= 1)
            acc[b] += __shfl_xor_sync(0xffffffffu, acc[b], off);
    }
    float bias = bd[n];
    if (lane < BB) g_decfea[lane*NN + n] = acc[lane] + bias;
}

// ---------------------------------------------------------------------------
// Kernel 2: fused scores + online softmax + context partial (flash-style).
// grid (SPL, BB) = 512 CTAs; 256 threads; 2 CTAs/SM. enc is staged through a
// 3-stage cp.async smem pipeline (32 KB/stage = 4 timestep rows); compute
// reads via LDS. Register count stays low -> no spills.
// ---------------------------------------------------------------------------
__global__ __launch_bounds__(THR, 2) void k_main(
    const float* __restrict__ enc,
    const float* __restrict__ cov,
    const float* __restrict__ wc,
    const float* __restrict__ v)
{
    extern __shared__ float smem[];
    float* sbuf = smem;                          // STAGES * 4*NN floats (96 KB)
    float* scov = sbuf + STAGES*4*NN;            // CHUNK floats
    unsigned char* smask = (unsigned char*)(scov + CHUNK);   // CHUNK bytes
    float* sred = (float*)(smask + CHUNK);       // 8*5 floats
    float* sbc  = sred + 40;                     // 4 floats

    int tid  = threadIdx.x;
    int wid  = tid >> 5, lane = tid & 31;
    int sp = blockIdx.x, b = blockIdx.y;
    int t0 = sp * CHUNK;

    if (tid < CHUNK){
        scov[tid]  = cov[(t0 + tid)*BB + b];
        smask[tid] = g_mask8[(t0 + tid)*BB + b];
    }
    int n0 = tid * 8;
    float4 df0 = *(const float4*)(g_decfea + b*NN + n0);
    float4 df1 = *(const float4*)(g_decfea + b*NN + n0 + 4);
    float4 w0  = *(const float4*)(wc + n0);
    float4 w1  = *(const float4*)(wc + n0 + 4);
    float4 v0  = *(const float4*)(v + n0);
    float4 v1  = *(const float4*)(v + n0 + 4);

    float m = -INFINITY, Z = 0.f;
    float4 A0 = make_float4(0.f,0.f,0.f,0.f);
    float4 A1 = make_float4(0.f,0.f,0.f,0.f);

    const size_t encbase = (size_t)b*NN;
    // copy helper mapping: thread handles 8 float4s per stage
    // f = tid + j*256; row i = f>>9; n4 = f&511
    #define ISSUE_STAGE(stg, trow0)                                          \
        {                                                                    \
            unsigned int sb = (unsigned int)__cvta_generic_to_shared(        \
                              sbuf + (stg)*(4*NN));                          \
            _Pragma("unroll")                                                \
            for (int j = 0; j < 8; ++j){                                     \
                int f  = tid + j*256;                                        \
                int ri = f >> 9, n4 = f & 511;                               \
                const float* gp = enc + ((size_t)((trow0) + ri)*BB)*NN       \
                                      + encbase + n4*4;                      \
                cpasync16(sb + (unsigned int)((ri*NN + n4*4)*4), gp);        \
            }                                                                \
            CP_COMMIT();                                                     \
        }

    // prologue: issue stages for data 0 and 1
    ISSUE_STAGE(0, t0);
    ISSUE_STAGE(1, t0 + 4);
    CP_WAIT(1);          // data 0 complete (own groups)
    __syncthreads();     // visibility + scov/smask ready

    const int NB = CHUNK/4;   // 16
    for (int it = 0; it < NB; ++it){
        int cur = it % STAGES;
        int tb = t0 + it*4;
        const float* stage = sbuf + cur*(4*NN);

        // ---- phase A: per-thread partial dot for 4 timesteps (LDS) ----
        float part[4];
        #pragma unroll
        for (int i = 0; i < 4; ++i){
            const float4* rp = (const float4*)(stage + i*NN + n0);
            float4 ca = rp[0], cb = rp[1];
            float cv = scov[it*4 + i];
            float p;
            p  = tanhfast(fmaf(cv, w0.x, ca.x + df0.x)) * v0.x;
            p += tanhfast(fmaf(cv, w0.y, ca.y + df0.y)) * v0.y;
            p += tanhfast(fmaf(cv, w0.z, ca.z + df0.z)) * v0.z;
            p += tanhfast(fmaf(cv, w0.w, ca.w + df0.w)) * v0.w;
            p += tanhfast(fmaf(cv, w1.x, cb.x + df1.x)) * v1.x;
            p += tanhfast(fmaf(cv, w1.y, cb.y + df1.y)) * v1.y;
            p += tanhfast(fmaf(cv, w1.z, cb.z + df1.z)) * v1.z;
            p += tanhfast(fmaf(cv, w1.w, cb.w + df1.w)) * v1.w;
            part[i] = p;
        }
        // ---- phase B: warp reduce; R1 barrier (also releases buf it-1) ----
        #pragma unroll
        for (int i = 0; i < 4; ++i)
            #pragma unroll
            for (int off = 16; off; off >>= 1)
                part[i] += __shfl_xor_sync(0xffffffffu, part[i], off);
        if (lane == 0){
            #pragma unroll
            for (int i = 0; i < 4; ++i) sred[wid*5 + i] = part[i];
        }
        __syncthreads();   // R1

        // ---- phase C: stage-2 reduce + issue prefetch of data it+2 ----
        if (tid < 32){
            int s  = tid >> 3;             // score 0..3
            int ww = tid & 7;              // warp 0..7
            float val = sred[ww*5 + s];
            val += __shfl_xor_sync(0xffffffffu, val, 1);
            val += __shfl_xor_sync(0xffffffffu, val, 2);
            val += __shfl_xor_sync(0xffffffffu, val, 4);
            if (ww == 0) sbc[s] = val;
        }
        if (it + 2 < NB){
            int stg = (it + 2) % STAGES;   // == (it-1)%STAGES, released at R1
            ISSUE_STAGE(stg, tb + 8);
        }
        __syncthreads();   // R2

        // ---- phase E: softmax update + context accumulate (LDS re-read) ----
        float s[4];
        #pragma unroll
        for (int i = 0; i < 4; ++i)
            s[i] = smask[it*4 + i] ? -INFINITY : sbc[i];
        if (tid < 4) g_scores[(tb + tid)*BB + b] = s[tid];

        float m2 = m;
        #pragma unroll
        for (int i = 0; i < 4; ++i) m2 = fmaxf(m2, s[i]);
        if (m2 != -INFINITY){
            float sc = __expf(m - m2);             // m==-inf -> 0 (A still 0)
            float p[4];
            #pragma unroll
            for (int i = 0; i < 4; ++i) p[i] = __expf(s[i] - m2);
            Z = Z*sc + (p[0]+p[1]) + (p[2]+p[3]);
            float ax = A0.x*sc, ay = A0.y*sc, az = A0.z*sc, aw = A0.w*sc;
            float bx = A1.x*sc, by = A1.y*sc, bz = A1.z*sc, bw = A1.w*sc;
            #pragma unroll
            for (int i = 0; i < 4; ++i){
                const float4* rp = (const float4*)(stage + i*NN + n0);
                float4 ca = rp[0], cb = rp[1];
                ax = fmaf(p[i], ca.x, ax); ay = fmaf(p[i], ca.y, ay);
                az = fmaf(p[i], ca.z, az); aw = fmaf(p[i], ca.w, aw);
                bx = fmaf(p[i], cb.x, bx); by = fmaf(p[i], cb.y, by);
                bz = fmaf(p[i], cb.z, bz); bw = fmaf(p[i], cb.w, bw);
            }
            A0 = make_float4(ax, ay, az, aw);
            A1 = make_float4(bx, by, bz, bw);
            m = m2;
        }

        // ---- phase F: retire next stage + visibility barrier ----
        if (it + 1 < NB){
            if (it + 2 < NB) { CP_WAIT(1); } else { CP_WAIT(0); }
            __syncthreads();   // B1: stage it+1 visible to all
        }
    }
    if (tid == 0){
        g_m[b*SPL + sp] = m;
        g_z[b*SPL + sp] = Z;
    }
    float4* op = (float4*)(g_acc + (size_t)(b*SPL + sp)*NN + n0);
    op[0] = A0; op[1] = A1;
    #undef ISSUE_STAGE
}

// ---------------------------------------------------------------------------
// Kernel 3: combine. blocks 0..31: context c[b, n-half] (32 split partials,
// 32-deep load ILP). blocks 32..159: attn + coverage, float4 flat-indexed.
// ---------------------------------------------------------------------------
__global__ void k_combine(const float* __restrict__ cov,
                          float* __restrict__ out){
    int tid = threadIdx.x;
    if (blockIdx.x < 2*BB){
        // ---- context for batch b, n-half h ----
        int b = blockIdx.x >> 1, h = blockIdx.x & 1;
        __shared__ float sw[SPL];
        if (tid < 32){
            float mv = g_m[b*SPL + tid];
            float zv = g_z[b*SPL + tid];
            float M = mv;
            #pragma unroll
            for (int off = 16; off; off >>= 1)
                M = fmaxf(M, __shfl_xor_sync(0xffffffffu, M, off));
            float Zs = zv * __expf(mv - M);
            #pragma unroll
            for (int off = 16; off; off >>= 1)
                Zs += __shfl_xor_sync(0xffffffffu, Zs, off);
            float inv = 1.0f / Zs;
            sw[tid] = __expf(mv - M) * inv;
        }
        __syncthreads();
        int n0 = h*1024 + tid*4;
        float4 r = make_float4(0.f,0.f,0.f,0.f);
        #pragma unroll
        for (int s = 0; s < SPL; ++s){
            float4 x = *(const float4*)(g_acc + (size_t)(b*SPL + s)*NN + n0);
            float wgt = sw[s];
            r.x = fmaf(wgt, x.x, r.x); r.y = fmaf(wgt, x.y, r.y);
            r.z = fmaf(wgt, x.z, r.z); r.w = fmaf(wgt, x.w, r.w);
        }
        *(float4*)(out + b*NN + n0) = r;
    } else {
        // ---- attn_dist + coverage_out, float4-flat-indexed ----
        __shared__ float sM[BB], sInv[BB];
        if (tid < BB){
            int b = tid;
            float M = -INFINITY;
            #pragma unroll
            for (int s = 0; s < SPL; ++s) M = fmaxf(M, g_m[b*SPL + s]);
            float Zs = 0.f;
            #pragma unroll
            for (int s = 0; s < SPL; ++s) Zs += g_z[b*SPL + s] * __expf(g_m[b*SPL + s] - M);
            sM[b] = M; sInv[b] = 1.0f / Zs;
        }
        __syncthreads();
        int q = (blockIdx.x - 2*BB) * 256 + tid;    // 128 blocks -> 8192 quads
        int flat = q * 4;                           // covers TT*BB floats
        if (q < (TT*BB)/4){
            float4 sc = *(const float4*)(g_scores + flat);
            float4 cv = *(const float4*)(cov + flat);
            int b0 = flat & (BB-1);                 // 4 consecutive batches
            float4 a;
            a.x = __expf(sc.x - sM[b0  ]) * sInv[b0  ];
            a.y = __expf(sc.y - sM[b0+1]) * sInv[b0+1];
            a.z = __expf(sc.z - sM[b0+2]) * sInv[b0+2];
            a.w = __expf(sc.w - sM[b0+3]) * sInv[b0+3];
            *(float4*)(out + BB*NN + flat) = a;
            float4 cg = make_float4(cv.x + a.x, cv.y + a.y, cv.z + a.z, cv.w + a.w);
            *(float4*)(out + BB*NN + TT*BB + flat) = cg;
        }
    }
}

// ---------------------------------------------------------------------------
extern "C" void kernel_launch(void* const* d_in, const int* in_sizes, int n_in,
                              void* d_out, int out_size){
    const float*         dec  = (const float*)d_in[0];          // [B,H]
    const float*         enc  = (const float*)d_in[1];          // [T,B,N]
    const unsigned char* mask = (const unsigned char*)d_in[2];  // [T,B] (dtype auto-detected)
    const float*         cov  = (const float*)d_in[3];          // [T,B]
    const float*         Wd   = (const float*)d_in[4];          // [N,H]
    const float*         bd   = (const float*)d_in[5];          // [N]
    const float*         wc   = (const float*)d_in[6];          // [N]
    const float*         v    = (const float*)d_in[7];          // [N]
    float* out = (float*)d_out;  // c[B,N] | attn[T,B] | coverage_out[T,B]

    const int SMEM_DEC  = BB*HH*4;                              // 64 KB
    const int SMEM_MAIN = (STAGES*4*NN + CHUNK)*4 + CHUNK + 40*4 + 4*4;  // ~98.8 KB

    cudaFuncSetAttribute(k_decfea, cudaFuncAttributeMaxDynamicSharedMemorySize, SMEM_DEC);
    cudaFuncSetAttribute(k_main,   cudaFuncAttributeMaxDynamicSharedMemorySize, SMEM_MAIN);

    k_decfea<<<256, 256, SMEM_DEC>>>(dec, Wd, bd, mask);
    k_main<<<dim3(SPL, BB), THR, SMEM_MAIN>>>(enc, cov, wc, v);
    k_combine<<<2*BB + (TT*BB/4 + 255)/256, 256>>>(cov, out);
}